// round 1
// baseline (speedup 1.0000x reference)
#include <cuda_runtime.h>
#include <cuda_bf16.h>

#define TT 12
#define CC 32
#define MAXN 131072

// ---- scratch (static device globals; no allocation allowed) ----
__device__ float g_deg[MAXN];
__device__ float g_dinv[MAXN];
__device__ float g_agg[MAXN * TT];
__device__ float g_az[CC], g_ah[CC], g_bz[CC], g_bh[CC];
__device__ float g_probs[TT];
__device__ float g_hw[CC];
__device__ float g_hb;

// ---- K1: deg init (self-loop weight 1) ----
__global__ void k_init_deg(int n) {
    int i = blockIdx.x * blockDim.x + threadIdx.x;
    if (i < n) g_deg[i] = 1.0f;
}

// ---- K2: deg accumulation over edges ----
__global__ void k_deg(const int* __restrict__ ei, const float* __restrict__ ew, int e) {
    int i = blockIdx.x * blockDim.x + threadIdx.x;
    if (i < e) atomicAdd(&g_deg[ei[e + i]], ew[i]);   // destination = edge_index[1]
}

// ---- K3: dinv + agg initialized with self-loop contribution ----
__global__ void k_dinv_agginit(const float* __restrict__ x, int n) {
    int i = blockIdx.x * blockDim.x + threadIdx.x;
    if (i >= n) return;
    float dg = g_deg[i];
    float di = dg > 0.0f ? rsqrtf(dg) : 0.0f;
    g_dinv[i] = di;
    float sl = di * di;          // norm of self loop: dinv * 1 * dinv
    const float4* xr = reinterpret_cast<const float4*>(x + (size_t)i * TT);
    float4 v0 = xr[0], v1 = xr[1], v2 = xr[2];
    float4* ar = reinterpret_cast<float4*>(g_agg + (size_t)i * TT);
    ar[0] = make_float4(sl * v0.x, sl * v0.y, sl * v0.z, sl * v0.w);
    ar[1] = make_float4(sl * v1.x, sl * v1.y, sl * v1.z, sl * v1.w);
    ar[2] = make_float4(sl * v2.x, sl * v2.y, sl * v2.z, sl * v2.w);
}

// vectorized global reduction (sm_90+): 4 floats per op
__device__ __forceinline__ void red4(float* p, float a, float b, float c, float d) {
    asm volatile("red.global.add.v4.f32 [%0], {%1, %2, %3, %4};"
                 :: "l"(p), "f"(a), "f"(b), "f"(c), "f"(d) : "memory");
}

// ---- K4: edge scatter  agg[d,:] += norm * x[s,:] ----
__global__ void k_scatter(const int* __restrict__ ei, const float* __restrict__ ew,
                          const float* __restrict__ x, int e) {
    int i = blockIdx.x * blockDim.x + threadIdx.x;
    if (i >= e) return;
    int s = __ldg(ei + i);
    int d = __ldg(ei + e + i);
    float nrm = g_dinv[s] * __ldg(ew + i) * g_dinv[d];
    const float4* xs = reinterpret_cast<const float4*>(x + (size_t)s * TT);
    float4 v0 = __ldg(xs + 0), v1 = __ldg(xs + 1), v2 = __ldg(xs + 2);
    float* ag = g_agg + (size_t)d * TT;
    red4(ag + 0, nrm * v0.x, nrm * v0.y, nrm * v0.z, nrm * v0.w);
    red4(ag + 4, nrm * v1.x, nrm * v1.y, nrm * v1.z, nrm * v1.w);
    red4(ag + 8, nrm * v2.x, nrm * v2.y, nrm * v2.z, nrm * v2.w);
}

// ---- K5: fold all dense params into 32-wide affine coefficients ----
// Z[n,t,o] = sigmoid(agg*Az[o] + Bz[o]),  Az[o]=sum_c w_z[c]*lw_z[o,c],
// Bz[o]=sum_c b_z[c]*lw_z[o,c] + lb_z[o]  (same for H). probs = softmax(att).
__global__ void k_consts(const float* __restrict__ w_z, const float* __restrict__ b_z,
                         const float* __restrict__ w_h, const float* __restrict__ b_h,
                         const float* __restrict__ lw_z, const float* __restrict__ lb_z,
                         const float* __restrict__ lw_h, const float* __restrict__ lb_h,
                         const float* __restrict__ att,
                         const float* __restrict__ head_w, const float* __restrict__ head_b) {
    int o = threadIdx.x;
    if (o < CC) {
        float az = 0.f, bz = 0.f, ah = 0.f, bh = 0.f;
        const float* rz = lw_z + o * 2 * CC;   // torch layout [C, 2C]; first C cols used
        const float* rh = lw_h + o * 2 * CC;
        #pragma unroll
        for (int c = 0; c < CC; c++) {
            az += w_z[c] * rz[c];
            bz += b_z[c] * rz[c];
            ah += w_h[c] * rh[c];
            bh += b_h[c] * rh[c];
        }
        g_az[o] = az; g_bz[o] = bz + lb_z[o];
        g_ah[o] = ah; g_bh[o] = bh + lb_h[o];
        g_hw[o] = head_w[o];
    }
    if (o == 0) {
        float m = -1e30f;
        for (int t = 0; t < TT; t++) m = fmaxf(m, att[t]);
        float ex[TT]; float sum = 0.f;
        for (int t = 0; t < TT; t++) { ex[t] = expf(att[t] - m); sum += ex[t]; }
        for (int t = 0; t < TT; t++) g_probs[t] = ex[t] / sum;
        g_hb = head_b[0];
    }
}

// ---- K6: pointwise GRU-collapse + temporal attention + head ----
__global__ void k_final(float* __restrict__ out, int n) {
    int i = blockIdx.x * blockDim.x + threadIdx.x;
    if (i >= n) return;
    const float4* ap = reinterpret_cast<const float4*>(g_agg + (size_t)i * TT);
    float4 a0 = ap[0], a1 = ap[1], a2 = ap[2];
    float a[TT] = {a0.x, a0.y, a0.z, a0.w, a1.x, a1.y, a1.z, a1.w, a2.x, a2.y, a2.z, a2.w};
    float p[TT];
    #pragma unroll
    for (int t = 0; t < TT; t++) p[t] = g_probs[t];
    float acc = g_hb;
    #pragma unroll 2
    for (int c = 0; c < CC; c++) {
        float az = g_az[c], bz = g_bz[c], ah = g_ah[c], bh = g_bh[c];
        float hw = g_hw[c];
        float hc = 0.f;
        #pragma unroll
        for (int t = 0; t < TT; t++) {
            float zarg = fmaf(a[t], az, bz);
            float z = __fdividef(1.0f, 1.0f + __expf(-zarg));     // sigmoid
            float harg = fmaf(a[t], ah, bh);
            float eh = __expf(2.0f * harg);
            float th = 1.0f - __fdividef(2.0f, eh + 1.0f);        // tanh
            hc = fmaf(p[t], (1.0f - z) * th, hc);
        }
        acc = fmaf(fmaxf(hc, 0.f), hw, acc);
    }
    out[i] = acc;
}

extern "C" void kernel_launch(void* const* d_in, const int* in_sizes, int n_in,
                              void* d_out, int out_size) {
    const float* x      = (const float*)d_in[0];
    const int*   ei     = (const int*)  d_in[1];
    const float* ew     = (const float*)d_in[2];
    const float* w_z    = (const float*)d_in[3];
    const float* b_z    = (const float*)d_in[4];
    // d_in[5], d_in[6]: w_r, b_r — reset gate multiplies H=0, unused
    const float* w_h    = (const float*)d_in[7];
    const float* b_h    = (const float*)d_in[8];
    const float* lw_z   = (const float*)d_in[9];
    const float* lb_z   = (const float*)d_in[10];
    // d_in[11], d_in[12]: lw_r, lb_r — unused
    const float* lw_h   = (const float*)d_in[13];
    const float* lb_h   = (const float*)d_in[14];
    const float* att    = (const float*)d_in[15];
    const float* head_w = (const float*)d_in[16];
    const float* head_b = (const float*)d_in[17];
    float* out = (float*)d_out;

    int n = in_sizes[0] / TT;       // x is [N, T]
    int e = in_sizes[2];            // edge_weight is [E]
    if (n > MAXN) n = MAXN;

    const int B = 256;
    int gn = (n + B - 1) / B;
    int ge = (e + B - 1) / B;

    k_init_deg<<<gn, B>>>(n);
    k_consts<<<1, 32>>>(w_z, b_z, w_h, b_h, lw_z, lb_z, lw_h, lb_h, att, head_w, head_b);
    k_deg<<<ge, B>>>(ei, ew, e);
    k_dinv_agginit<<<gn, B>>>(x, n);
    k_scatter<<<ge, B>>>(ei, ew, x, e);
    k_final<<<gn, B>>>(out, n);
}

// round 2
// speedup vs baseline: 1.3077x; 1.3077x over previous
#include <cuda_runtime.h>
#include <cuda_bf16.h>

#define TT 12
#define CC 32
#define MAXN 131072

// ---- scratch (static device globals; no allocation allowed) ----
__device__ float g_deg[MAXN];
__device__ float g_dinv[MAXN];
__device__ float g_y[MAXN * TT];      // y[s,t] = dinv[s] * x[s,t]
__device__ float g_agg[MAXN * TT];    // pre-dinv[d] aggregation
__device__ float g_az[CC], g_ah[CC], g_bz[CC], g_bh[CC];
__device__ float g_probs[TT];         // 0.5 * softmax(att)
__device__ float g_hw[CC];
__device__ float g_hb;

__device__ __forceinline__ float tanh_fast(float x) {
    float y;
    asm("tanh.approx.f32 %0, %1;" : "=f"(y) : "f"(x));
    return y;
}

// ---- K1: deg init (self-loop weight 1) ----
__global__ void k_init_deg(int n) {
    int i = blockIdx.x * blockDim.x + threadIdx.x;
    if (i < n) g_deg[i] = 1.0f;
}

// ---- K2: deg accumulation over edges (4 edges/thread, vectorized loads) ----
__global__ void k_deg4(const int* __restrict__ ei, const float* __restrict__ ew, int e) {
    int i4 = blockIdx.x * blockDim.x + threadIdx.x;
    int base = i4 * 4;
    if (base + 3 < e) {
        int4   d = *reinterpret_cast<const int4*>(ei + e + base);
        float4 w = *reinterpret_cast<const float4*>(ew + base);
        atomicAdd(&g_deg[d.x], w.x);
        atomicAdd(&g_deg[d.y], w.y);
        atomicAdd(&g_deg[d.z], w.z);
        atomicAdd(&g_deg[d.w], w.w);
    } else {
        for (int i = base; i < e; i++) atomicAdd(&g_deg[ei[e + i]], ew[i]);
    }
}

// ---- K3: dinv + y = dinv*x ; agg init = self-loop term dinv[d]*x[d] (pre outer dinv) ----
__global__ void k_dinv_y(const float* __restrict__ x, int n) {
    int i = blockIdx.x * blockDim.x + threadIdx.x;
    if (i >= n) return;
    float dg = g_deg[i];
    float di = dg > 0.0f ? rsqrtf(dg) : 0.0f;
    g_dinv[i] = di;
    const float4* xr = reinterpret_cast<const float4*>(x + (size_t)i * TT);
    float4 v0 = xr[0], v1 = xr[1], v2 = xr[2];
    float4 y0 = make_float4(di * v0.x, di * v0.y, di * v0.z, di * v0.w);
    float4 y1 = make_float4(di * v1.x, di * v1.y, di * v1.z, di * v1.w);
    float4 y2 = make_float4(di * v2.x, di * v2.y, di * v2.z, di * v2.w);
    float4* yr = reinterpret_cast<float4*>(g_y + (size_t)i * TT);
    yr[0] = y0; yr[1] = y1; yr[2] = y2;
    float4* ar = reinterpret_cast<float4*>(g_agg + (size_t)i * TT);
    ar[0] = y0; ar[1] = y1; ar[2] = y2;   // self-loop: dinv[d]*1*x[d] (outer dinv applied in k_final)
}

// vectorized global reduction: 4 floats per op
__device__ __forceinline__ void red4(float* p, float a, float b, float c, float d) {
    asm volatile("red.global.add.v4.f32 [%0], {%1, %2, %3, %4};"
                 :: "l"(p), "f"(a), "f"(b), "f"(c), "f"(d) : "memory");
}

// ---- K4: edge scatter  agg[d,:] += w * y[s,:]   (no dinv loads) ----
__global__ void k_scatter(const int* __restrict__ ei, const float* __restrict__ ew,
                          int e) {
    int i = blockIdx.x * blockDim.x + threadIdx.x;
    if (i >= e) return;
    int s = __ldg(ei + i);
    int d = __ldg(ei + e + i);
    float w = __ldg(ew + i);
    const float4* ys = reinterpret_cast<const float4*>(g_y + (size_t)s * TT);
    float4 v0 = __ldg(ys + 0), v1 = __ldg(ys + 1), v2 = __ldg(ys + 2);
    float* ag = g_agg + (size_t)d * TT;
    red4(ag + 0, w * v0.x, w * v0.y, w * v0.z, w * v0.w);
    red4(ag + 4, w * v1.x, w * v1.y, w * v1.z, w * v1.w);
    red4(ag + 8, w * v2.x, w * v2.y, w * v2.z, w * v2.w);
}

// ---- K5: fold dense params into 32-wide affine coefficients ----
__global__ void k_consts(const float* __restrict__ w_z, const float* __restrict__ b_z,
                         const float* __restrict__ w_h, const float* __restrict__ b_h,
                         const float* __restrict__ lw_z, const float* __restrict__ lb_z,
                         const float* __restrict__ lw_h, const float* __restrict__ lb_h,
                         const float* __restrict__ att,
                         const float* __restrict__ head_w, const float* __restrict__ head_b) {
    int o = threadIdx.x;
    if (o < CC) {
        float az = 0.f, bz = 0.f, ah = 0.f, bh = 0.f;
        const float* rz = lw_z + o * 2 * CC;   // torch layout [C, 2C]; first C cols used
        const float* rh = lw_h + o * 2 * CC;
        #pragma unroll
        for (int c = 0; c < CC; c++) {
            az += w_z[c] * rz[c];
            bz += b_z[c] * rz[c];
            ah += w_h[c] * rh[c];
            bh += b_h[c] * rh[c];
        }
        g_az[o] = az; g_bz[o] = bz + lb_z[o];
        g_ah[o] = ah; g_bh[o] = bh + lb_h[o];
        g_hw[o] = head_w[o];
    }
    if (o == 0) {
        float m = -1e30f;
        for (int t = 0; t < TT; t++) m = fmaxf(m, att[t]);
        float ex[TT]; float sum = 0.f;
        for (int t = 0; t < TT; t++) { ex[t] = expf(att[t] - m); sum += ex[t]; }
        for (int t = 0; t < TT; t++) g_probs[t] = 0.5f * ex[t] / sum;  // fold the 0.5 of (1-z)
        g_hb = head_b[0];
    }
}

// ---- K6: pointwise GRU-collapse + temporal attention + head ----
// sigmoid(x) = 0.5 + 0.5*tanh(x/2)  =>  (1-z) = 0.5*(1 - tanh(zarg/2))
// contribution = probs_t * (1-z) * tanh(harg); 0.5 folded into g_probs.
__global__ void k_final(float* __restrict__ out, int n) {
    int i = blockIdx.x * blockDim.x + threadIdx.x;
    if (i >= n) return;
    float di = g_dinv[i];   // outer dinv[d] factor
    const float4* ap = reinterpret_cast<const float4*>(g_agg + (size_t)i * TT);
    float4 a0 = ap[0], a1 = ap[1], a2 = ap[2];
    float a[TT] = {di*a0.x, di*a0.y, di*a0.z, di*a0.w,
                   di*a1.x, di*a1.y, di*a1.z, di*a1.w,
                   di*a2.x, di*a2.y, di*a2.z, di*a2.w};
    float p[TT];
    #pragma unroll
    for (int t = 0; t < TT; t++) p[t] = g_probs[t];
    float acc = g_hb;
    #pragma unroll 2
    for (int c = 0; c < CC; c++) {
        float az = 0.5f * g_az[c], bz = 0.5f * g_bz[c];
        float ah = g_ah[c], bh = g_bh[c];
        float hw = g_hw[c];
        float hc = 0.f;
        #pragma unroll
        for (int t = 0; t < TT; t++) {
            float tz = tanh_fast(fmaf(a[t], az, bz));      // tanh(zarg/2)
            float th = tanh_fast(fmaf(a[t], ah, bh));
            hc = fmaf(p[t], (1.0f - tz) * th, hc);
        }
        acc = fmaf(fmaxf(hc, 0.f), hw, acc);
    }
    out[i] = acc;
}

extern "C" void kernel_launch(void* const* d_in, const int* in_sizes, int n_in,
                              void* d_out, int out_size) {
    const float* x      = (const float*)d_in[0];
    const int*   ei     = (const int*)  d_in[1];
    const float* ew     = (const float*)d_in[2];
    const float* w_z    = (const float*)d_in[3];
    const float* b_z    = (const float*)d_in[4];
    // d_in[5], d_in[6]: w_r, b_r — reset gate multiplies H=0, unused
    const float* w_h    = (const float*)d_in[7];
    const float* b_h    = (const float*)d_in[8];
    const float* lw_z   = (const float*)d_in[9];
    const float* lb_z   = (const float*)d_in[10];
    // d_in[11], d_in[12]: lw_r, lb_r — unused
    const float* lw_h   = (const float*)d_in[13];
    const float* lb_h   = (const float*)d_in[14];
    const float* att    = (const float*)d_in[15];
    const float* head_w = (const float*)d_in[16];
    const float* head_b = (const float*)d_in[17];
    float* out = (float*)d_out;

    int n = in_sizes[0] / TT;       // x is [N, T]
    int e = in_sizes[2];            // edge_weight is [E]
    if (n > MAXN) n = MAXN;

    const int B = 256;
    int gn = (n + B - 1) / B;
    int ge = (e + B - 1) / B;
    int ge4 = ((e + 3) / 4 + B - 1) / B;

    k_init_deg<<<gn, B>>>(n);
    k_consts<<<1, 32>>>(w_z, b_z, w_h, b_h, lw_z, lb_z, lw_h, lb_h, att, head_w, head_b);
    k_deg4<<<ge4, B>>>(ei, ew, e);
    k_dinv_y<<<gn, B>>>(x, n);
    k_scatter<<<ge, B>>>(ei, ew, e);
    k_final<<<gn, B>>>(out, n);
}

// round 3
// speedup vs baseline: 1.3109x; 1.0025x over previous
#include <cuda_runtime.h>
#include <cuda_bf16.h>

#define TT 12
#define CC 32
#define MAXN 131072

// ---- scratch (static device globals; no allocation allowed) ----
__device__ float g_deg[MAXN];          // Σ incoming w (memset 0 each call); self-loop +1 folded into rsqrt
__device__ float g_dinv[MAXN];
__device__ float g_y[MAXN * TT];       // y[s,t] = dinv[s] * x[s,t]
__device__ float g_agg[MAXN * TT];     // scattered Σ w*y[s]  (memset 0 each call)
__device__ float g_az[CC], g_ah[CC], g_bz[CC], g_bh[CC];
__device__ float g_probs[TT];          // 0.5 * softmax(att)
__device__ float g_hw[CC];
__device__ float g_hb;

__device__ __forceinline__ float tanh_fast(float x) {
    float y;
    asm("tanh.approx.f32 %0, %1;" : "=f"(y) : "f"(x));
    return y;
}

// vectorized global reduction: 4 floats per op
__device__ __forceinline__ void red4(float* p, float a, float b, float c, float d) {
    asm volatile("red.global.add.v4.f32 [%0], {%1, %2, %3, %4};"
                 :: "l"(p), "f"(a), "f"(b), "f"(c), "f"(d) : "memory");
}

// ---- K1: fold dense params into 32-wide affine coefficients ----
__global__ void k_consts(const float* __restrict__ w_z, const float* __restrict__ b_z,
                         const float* __restrict__ w_h, const float* __restrict__ b_h,
                         const float* __restrict__ lw_z, const float* __restrict__ lb_z,
                         const float* __restrict__ lw_h, const float* __restrict__ lb_h,
                         const float* __restrict__ att,
                         const float* __restrict__ head_w, const float* __restrict__ head_b) {
    int o = threadIdx.x;
    if (o < CC) {
        float az = 0.f, bz = 0.f, ah = 0.f, bh = 0.f;
        const float* rz = lw_z + o * 2 * CC;   // torch layout [C, 2C]; first C cols used
        const float* rh = lw_h + o * 2 * CC;
        #pragma unroll
        for (int c = 0; c < CC; c++) {
            az += w_z[c] * rz[c];
            bz += b_z[c] * rz[c];
            ah += w_h[c] * rh[c];
            bh += b_h[c] * rh[c];
        }
        g_az[o] = az; g_bz[o] = bz + lb_z[o];
        g_ah[o] = ah; g_bh[o] = bh + lb_h[o];
        g_hw[o] = head_w[o];
    }
    if (o == 0) {
        float m = -1e30f;
        for (int t = 0; t < TT; t++) m = fmaxf(m, att[t]);
        float ex[TT]; float sum = 0.f;
        for (int t = 0; t < TT; t++) { ex[t] = expf(att[t] - m); sum += ex[t]; }
        for (int t = 0; t < TT; t++) g_probs[t] = 0.5f * ex[t] / sum;  // fold 0.5 of (1-z)
        g_hb = head_b[0];
    }
}

// ---- K2: deg accumulation over edges (4 edges/thread, vectorized loads) ----
__global__ void k_deg4(const int* __restrict__ ei, const float* __restrict__ ew, int e) {
    int i4 = blockIdx.x * blockDim.x + threadIdx.x;
    int base = i4 * 4;
    if (base + 3 < e) {
        int4   d = *reinterpret_cast<const int4*>(ei + e + base);
        float4 w = *reinterpret_cast<const float4*>(ew + base);
        atomicAdd(&g_deg[d.x], w.x);
        atomicAdd(&g_deg[d.y], w.y);
        atomicAdd(&g_deg[d.z], w.z);
        atomicAdd(&g_deg[d.w], w.w);
    } else {
        for (int i = base; i < e; i++) atomicAdd(&g_deg[ei[e + i]], ew[i]);
    }
}

// ---- K3: dinv + y = dinv*x ; one thread per float4 chunk (3 per node) ----
__global__ void k_dinv_y(const float* __restrict__ x, int n3) {
    int j = blockIdx.x * blockDim.x + threadIdx.x;
    if (j >= n3) return;
    int node = j / 3;
    int part = j - node * 3;
    float di = rsqrtf(1.0f + g_deg[node]);   // +1 = self-loop weight; always > 0
    if (part == 0) g_dinv[node] = di;
    float4 v = __ldg(reinterpret_cast<const float4*>(x) + j);
    reinterpret_cast<float4*>(g_y)[j] = make_float4(di * v.x, di * v.y, di * v.z, di * v.w);
}

// ---- K4: edge scatter  agg[d,:] += w * y[s,:]   (2 edges/thread for MLP) ----
__global__ void k_scatter2(const int* __restrict__ ei, const float* __restrict__ ew, int e) {
    int i = (blockIdx.x * blockDim.x + threadIdx.x) * 2;
    if (i + 1 < e) {
        int2   s = *reinterpret_cast<const int2*>(ei + i);
        int2   d = *reinterpret_cast<const int2*>(ei + e + i);
        float2 w = *reinterpret_cast<const float2*>(ew + i);
        const float4* y0 = reinterpret_cast<const float4*>(g_y + (size_t)s.x * TT);
        const float4* y1 = reinterpret_cast<const float4*>(g_y + (size_t)s.y * TT);
        float4 a0 = __ldg(y0 + 0), a1 = __ldg(y0 + 1), a2 = __ldg(y0 + 2);
        float4 b0 = __ldg(y1 + 0), b1 = __ldg(y1 + 1), b2 = __ldg(y1 + 2);
        float* p0 = g_agg + (size_t)d.x * TT;
        float* p1 = g_agg + (size_t)d.y * TT;
        red4(p0 + 0, w.x * a0.x, w.x * a0.y, w.x * a0.z, w.x * a0.w);
        red4(p0 + 4, w.x * a1.x, w.x * a1.y, w.x * a1.z, w.x * a1.w);
        red4(p0 + 8, w.x * a2.x, w.x * a2.y, w.x * a2.z, w.x * a2.w);
        red4(p1 + 0, w.y * b0.x, w.y * b0.y, w.y * b0.z, w.y * b0.w);
        red4(p1 + 4, w.y * b1.x, w.y * b1.y, w.y * b1.z, w.y * b1.w);
        red4(p1 + 8, w.y * b2.x, w.y * b2.y, w.y * b2.z, w.y * b2.w);
    } else if (i < e) {
        int s = __ldg(ei + i);
        int d = __ldg(ei + e + i);
        float w = __ldg(ew + i);
        const float4* ys = reinterpret_cast<const float4*>(g_y + (size_t)s * TT);
        float4 v0 = __ldg(ys + 0), v1 = __ldg(ys + 1), v2 = __ldg(ys + 2);
        float* ag = g_agg + (size_t)d * TT;
        red4(ag + 0, w * v0.x, w * v0.y, w * v0.z, w * v0.w);
        red4(ag + 4, w * v1.x, w * v1.y, w * v1.z, w * v1.w);
        red4(ag + 8, w * v2.x, w * v2.y, w * v2.z, w * v2.w);
    }
}

// ---- K5: pointwise GRU-collapse + temporal attention + head ----
// a[t] = dinv * (agg[t] + y[t])   (self-loop folded: agg excludes it, y holds dinv*x)
// sigmoid(x) = 0.5 + 0.5*tanh(x/2)  =>  (1-z) = 0.5*(1 - tanh(zarg/2)); 0.5 in g_probs.
__global__ void k_final(float* __restrict__ out, int n) {
    int i = blockIdx.x * blockDim.x + threadIdx.x;
    if (i >= n) return;
    float di = g_dinv[i];
    const float4* ap = reinterpret_cast<const float4*>(g_agg + (size_t)i * TT);
    const float4* yp = reinterpret_cast<const float4*>(g_y + (size_t)i * TT);
    float4 a0 = ap[0], a1 = ap[1], a2 = ap[2];
    float4 y0 = yp[0], y1 = yp[1], y2 = yp[2];
    float a[TT] = {di*(a0.x+y0.x), di*(a0.y+y0.y), di*(a0.z+y0.z), di*(a0.w+y0.w),
                   di*(a1.x+y1.x), di*(a1.y+y1.y), di*(a1.z+y1.z), di*(a1.w+y1.w),
                   di*(a2.x+y2.x), di*(a2.y+y2.y), di*(a2.z+y2.z), di*(a2.w+y2.w)};
    float p[TT];
    #pragma unroll
    for (int t = 0; t < TT; t++) p[t] = g_probs[t];
    float acc = g_hb;
    #pragma unroll 2
    for (int c = 0; c < CC; c++) {
        float az = 0.5f * g_az[c], bz = 0.5f * g_bz[c];
        float ah = g_ah[c], bh = g_bh[c];
        float hw = g_hw[c];
        float hc = 0.f;
        #pragma unroll
        for (int t = 0; t < TT; t++) {
            float tz = tanh_fast(fmaf(a[t], az, bz));      // tanh(zarg/2)
            float th = tanh_fast(fmaf(a[t], ah, bh));
            hc = fmaf(p[t], (1.0f - tz) * th, hc);
        }
        acc = fmaf(fmaxf(hc, 0.f), hw, acc);
    }
    out[i] = acc;
}

extern "C" void kernel_launch(void* const* d_in, const int* in_sizes, int n_in,
                              void* d_out, int out_size) {
    const float* x      = (const float*)d_in[0];
    const int*   ei     = (const int*)  d_in[1];
    const float* ew     = (const float*)d_in[2];
    const float* w_z    = (const float*)d_in[3];
    const float* b_z    = (const float*)d_in[4];
    // d_in[5], d_in[6]: w_r, b_r — reset gate multiplies H=0, unused
    const float* w_h    = (const float*)d_in[7];
    const float* b_h    = (const float*)d_in[8];
    const float* lw_z   = (const float*)d_in[9];
    const float* lb_z   = (const float*)d_in[10];
    // d_in[11], d_in[12]: lw_r, lb_r — unused
    const float* lw_h   = (const float*)d_in[13];
    const float* lb_h   = (const float*)d_in[14];
    const float* att    = (const float*)d_in[15];
    const float* head_w = (const float*)d_in[16];
    const float* head_b = (const float*)d_in[17];
    float* out = (float*)d_out;

    int n = in_sizes[0] / TT;       // x is [N, T]
    int e = in_sizes[2];            // edge_weight is [E]
    if (n > MAXN) n = MAXN;

    // memset nodes (graph-capturable, no kernels)
    void* p_deg = nullptr; void* p_agg = nullptr;
    cudaGetSymbolAddress(&p_deg, g_deg);
    cudaGetSymbolAddress(&p_agg, g_agg);
    cudaMemsetAsync(p_deg, 0, (size_t)n * sizeof(float), 0);
    cudaMemsetAsync(p_agg, 0, (size_t)n * TT * sizeof(float), 0);

    const int B = 256;
    int gn  = (n + B - 1) / B;
    int n3  = n * 3;
    int gn3 = (n3 + B - 1) / B;
    int ge4 = ((e + 3) / 4 + B - 1) / B;
    int ge2 = ((e + 1) / 2 + B - 1) / B;

    k_consts<<<1, 32>>>(w_z, b_z, w_h, b_h, lw_z, lb_z, lw_h, lb_h, att, head_w, head_b);
    k_deg4<<<ge4, B>>>(ei, ew, e);
    k_dinv_y<<<gn3, B>>>(x, n3);
    k_scatter2<<<ge2, B>>>(ei, ew, e);
    k_final<<<gn, B>>>(out, n);
}

// round 4
// speedup vs baseline: 1.6179x; 1.2342x over previous
#include <cuda_runtime.h>
#include <cuda_bf16.h>

#define TT 12
#define CC 32
#define MAXN 131072

// ---- scratch (static device globals; zero-initialized at load; kept zeroed by k_final) ----
__device__ float g_deg[MAXN];          // Σ incoming w; self-loop +1 folded into rsqrt; re-zeroed by k_final
__device__ float g_dinv[MAXN];
__device__ float g_y[MAXN * TT];       // y[s,t] = dinv[s] * x[s,t]
__device__ float g_agg[MAXN * TT];     // scattered Σ w*y[s]; re-zeroed by k_final
__device__ float g_az[CC], g_ah[CC], g_bz[CC], g_bh[CC];
__device__ float g_probs[TT];          // 0.5 * softmax(att)
__device__ float g_hw[CC];
__device__ float g_hb;

__device__ __forceinline__ float tanh_fast(float x) {
    float y;
    asm("tanh.approx.f32 %0, %1;" : "=f"(y) : "f"(x));
    return y;
}

// vectorized global reduction: 4 floats per op
__device__ __forceinline__ void red4(float* p, float a, float b, float c, float d) {
    asm volatile("red.global.add.v4.f32 [%0], {%1, %2, %3, %4};"
                 :: "l"(p), "f"(a), "f"(b), "f"(c), "f"(d) : "memory");
}

// ---- K1: deg accumulation (blocks [0, degBlocks)) + consts fold (block degBlocks) ----
__global__ void k_deg_consts(const int* __restrict__ ei, const float* __restrict__ ew, int e,
                             int degBlocks,
                             const float* __restrict__ w_z, const float* __restrict__ b_z,
                             const float* __restrict__ w_h, const float* __restrict__ b_h,
                             const float* __restrict__ lw_z, const float* __restrict__ lb_z,
                             const float* __restrict__ lw_h, const float* __restrict__ lb_h,
                             const float* __restrict__ att,
                             const float* __restrict__ head_w, const float* __restrict__ head_b) {
    if (blockIdx.x < (unsigned)degBlocks) {
        int base = (blockIdx.x * blockDim.x + threadIdx.x) * 4;
        if (base + 3 < e) {
            int4   d = *reinterpret_cast<const int4*>(ei + e + base);
            float4 w = *reinterpret_cast<const float4*>(ew + base);
            atomicAdd(&g_deg[d.x], w.x);
            atomicAdd(&g_deg[d.y], w.y);
            atomicAdd(&g_deg[d.z], w.z);
            atomicAdd(&g_deg[d.w], w.w);
        } else {
            for (int i = base; i < e; i++) atomicAdd(&g_deg[ei[e + i]], ew[i]);
        }
        return;
    }
    // ---- consts block ----
    int o = threadIdx.x;
    if (o < CC) {
        float az = 0.f, bz = 0.f, ah = 0.f, bh = 0.f;
        const float* rz = lw_z + o * 2 * CC;   // torch layout [C, 2C]; first C cols used
        const float* rh = lw_h + o * 2 * CC;
        #pragma unroll
        for (int c = 0; c < CC; c++) {
            az += w_z[c] * rz[c];
            bz += b_z[c] * rz[c];
            ah += w_h[c] * rh[c];
            bh += b_h[c] * rh[c];
        }
        g_az[o] = az; g_bz[o] = bz + lb_z[o];
        g_ah[o] = ah; g_bh[o] = bh + lb_h[o];
        g_hw[o] = head_w[o];
    }
    if (o == 0) {
        float m = -1e30f;
        for (int t = 0; t < TT; t++) m = fmaxf(m, att[t]);
        float ex[TT]; float sum = 0.f;
        for (int t = 0; t < TT; t++) { ex[t] = expf(att[t] - m); sum += ex[t]; }
        for (int t = 0; t < TT; t++) g_probs[t] = 0.5f * ex[t] / sum;  // fold 0.5 of (1-z)
        g_hb = head_b[0];
    }
}

// ---- K2: dinv + y = dinv*x ; one thread per float4 chunk (3 per node) ----
__global__ void k_dinv_y(const float* __restrict__ x, int n3) {
    int j = blockIdx.x * blockDim.x + threadIdx.x;
    if (j >= n3) return;
    int node = j / 3;
    int part = j - node * 3;
    float di = rsqrtf(1.0f + g_deg[node]);   // +1 = self-loop weight; always > 0
    if (part == 0) g_dinv[node] = di;
    float4 v = __ldg(reinterpret_cast<const float4*>(x) + j);
    reinterpret_cast<float4*>(g_y)[j] = make_float4(di * v.x, di * v.y, di * v.z, di * v.w);
}

// ---- K3: cooperative 3-lane edge scatter  agg[d,:] += w * y[s,:] ----
// 3 lanes handle one edge (lane part p = float4 chunk p of the 48B row), so the
// gather and the RED for one row coalesce into single L1tex line-wavefronts.
// 30 lanes/warp used (10 edges per warp), lanes 30,31 idle.
__global__ void k_scatter3(const int* __restrict__ ei, const float* __restrict__ ew, int e) {
    int lane = threadIdx.x & 31;
    if (lane >= 30) return;
    int warp = (blockIdx.x * blockDim.x + threadIdx.x) >> 5;
    int grp  = lane / 3;               // 0..9
    int part = lane - grp * 3;         // 0..2
    int i = warp * 10 + grp;           // edge id
    if (i >= e) return;
    int s = __ldg(ei + i);
    int d = __ldg(ei + e + i);
    float w = __ldg(ew + i);
    float4 v = __ldg(reinterpret_cast<const float4*>(g_y + (size_t)s * TT) + part);
    red4(g_agg + (size_t)d * TT + part * 4, w * v.x, w * v.y, w * v.z, w * v.w);
}

// ---- K4: pointwise GRU-collapse + temporal attention + head; re-zeroes scratch ----
// a[t] = dinv * (agg[t] + y[t]);  sigmoid via tanh: (1-z) = 0.5*(1 - tanh(zarg/2))
__global__ void k_final(float* __restrict__ out, int n) {
    int i = blockIdx.x * blockDim.x + threadIdx.x;
    if (i >= n) return;
    float di = g_dinv[i];
    float4* ap = reinterpret_cast<float4*>(g_agg + (size_t)i * TT);
    const float4* yp = reinterpret_cast<const float4*>(g_y + (size_t)i * TT);
    float4 a0 = ap[0], a1 = ap[1], a2 = ap[2];
    float4 y0 = yp[0], y1 = yp[1], y2 = yp[2];
    // re-zero scratch for the next call (graph replays)
    float4 z4 = make_float4(0.f, 0.f, 0.f, 0.f);
    ap[0] = z4; ap[1] = z4; ap[2] = z4;
    g_deg[i] = 0.0f;
    float a[TT] = {di*(a0.x+y0.x), di*(a0.y+y0.y), di*(a0.z+y0.z), di*(a0.w+y0.w),
                   di*(a1.x+y1.x), di*(a1.y+y1.y), di*(a1.z+y1.z), di*(a1.w+y1.w),
                   di*(a2.x+y2.x), di*(a2.y+y2.y), di*(a2.z+y2.z), di*(a2.w+y2.w)};
    float p[TT];
    #pragma unroll
    for (int t = 0; t < TT; t++) p[t] = g_probs[t];
    float acc = g_hb;
    #pragma unroll 2
    for (int c = 0; c < CC; c++) {
        float az = 0.5f * g_az[c], bz = 0.5f * g_bz[c];
        float ah = g_ah[c], bh = g_bh[c];
        float hw = g_hw[c];
        float hc = 0.f;
        #pragma unroll
        for (int t = 0; t < TT; t++) {
            float tz = tanh_fast(fmaf(a[t], az, bz));      // tanh(zarg/2)
            float th = tanh_fast(fmaf(a[t], ah, bh));
            hc = fmaf(p[t], (1.0f - tz) * th, hc);
        }
        acc = fmaf(fmaxf(hc, 0.f), hw, acc);
    }
    out[i] = acc;
}

extern "C" void kernel_launch(void* const* d_in, const int* in_sizes, int n_in,
                              void* d_out, int out_size) {
    const float* x      = (const float*)d_in[0];
    const int*   ei     = (const int*)  d_in[1];
    const float* ew     = (const float*)d_in[2];
    const float* w_z    = (const float*)d_in[3];
    const float* b_z    = (const float*)d_in[4];
    // d_in[5], d_in[6]: w_r, b_r — reset gate multiplies H=0, unused
    const float* w_h    = (const float*)d_in[7];
    const float* b_h    = (const float*)d_in[8];
    const float* lw_z   = (const float*)d_in[9];
    const float* lb_z   = (const float*)d_in[10];
    // d_in[11], d_in[12]: lw_r, lb_r — unused
    const float* lw_h   = (const float*)d_in[13];
    const float* lb_h   = (const float*)d_in[14];
    const float* att    = (const float*)d_in[15];
    const float* head_w = (const float*)d_in[16];
    const float* head_b = (const float*)d_in[17];
    float* out = (float*)d_out;

    int n = in_sizes[0] / TT;       // x is [N, T]
    int e = in_sizes[2];            // edge_weight is [E]
    if (n > MAXN) n = MAXN;

    const int B = 256;
    int gn  = (n + B - 1) / B;
    int n3  = n * 3;
    int gn3 = (n3 + B - 1) / B;
    int degBlocks = ((e + 3) / 4 + B - 1) / B;
    // scatter: 10 edges per warp, 8 warps per 256-thread block -> 80 edges/block
    int gsc = (e + 79) / 80;

    k_deg_consts<<<degBlocks + 1, B>>>(ei, ew, e, degBlocks,
                                       w_z, b_z, w_h, b_h, lw_z, lb_z, lw_h, lb_h,
                                       att, head_w, head_b);
    k_dinv_y<<<gn3, B>>>(x, n3);
    k_scatter3<<<gsc, B>>>(ei, ew, e);
    k_final<<<gn, B>>>(out, n);
}

// round 5
// speedup vs baseline: 1.6542x; 1.0224x over previous
#include <cuda_runtime.h>
#include <cuda_bf16.h>

#define TT 12
#define CC 32
#define MAXN 131072

// ---- scratch (static device globals; zero-initialized at load; kept zeroed by k_final) ----
__device__ float g_deg[MAXN];          // Σ incoming w; self-loop +1 folded into rsqrt; re-zeroed by k_final
__device__ float g_dinv[MAXN];
__device__ float g_y[MAXN * TT];       // y[s,t] = dinv[s] * x[s,t]
__device__ float g_agg[MAXN * TT];     // scattered Σ w*y[s]; re-zeroed by k_final
__device__ float g_az[CC], g_ah[CC], g_bz[CC], g_bh[CC];
__device__ float g_probs[TT];          // 0.5 * softmax(att)
__device__ float g_hw[CC];
__device__ float g_hb;

__device__ __forceinline__ float tanh_fast(float x) {
    float y;
    asm("tanh.approx.f32 %0, %1;" : "=f"(y) : "f"(x));
    return y;
}

// vectorized global reduction: 4 floats per op
__device__ __forceinline__ void red4(float* p, float a, float b, float c, float d) {
    asm volatile("red.global.add.v4.f32 [%0], {%1, %2, %3, %4};"
                 :: "l"(p), "f"(a), "f"(b), "f"(c), "f"(d) : "memory");
}

// ---- K1: deg accumulation (blocks [0, degBlocks)) + consts fold (block degBlocks) ----
__global__ void k_deg_consts(const int* __restrict__ ei, const float* __restrict__ ew, int e,
                             int degBlocks,
                             const float* __restrict__ w_z, const float* __restrict__ b_z,
                             const float* __restrict__ w_h, const float* __restrict__ b_h,
                             const float* __restrict__ lw_z, const float* __restrict__ lb_z,
                             const float* __restrict__ lw_h, const float* __restrict__ lb_h,
                             const float* __restrict__ att,
                             const float* __restrict__ head_w, const float* __restrict__ head_b) {
    if (blockIdx.x < (unsigned)degBlocks) {
        int base = (blockIdx.x * blockDim.x + threadIdx.x) * 4;
        if (base + 3 < e) {
            int4   d = *reinterpret_cast<const int4*>(ei + e + base);
            float4 w = *reinterpret_cast<const float4*>(ew + base);
            atomicAdd(&g_deg[d.x], w.x);
            atomicAdd(&g_deg[d.y], w.y);
            atomicAdd(&g_deg[d.z], w.z);
            atomicAdd(&g_deg[d.w], w.w);
        } else {
            for (int i = base; i < e; i++) atomicAdd(&g_deg[ei[e + i]], ew[i]);
        }
        return;
    }
    // ---- consts block ----
    int o = threadIdx.x;
    if (o < CC) {
        float az = 0.f, bz = 0.f, ah = 0.f, bh = 0.f;
        const float* rz = lw_z + o * 2 * CC;   // torch layout [C, 2C]; first C cols used
        const float* rh = lw_h + o * 2 * CC;
        #pragma unroll
        for (int c = 0; c < CC; c++) {
            az += w_z[c] * rz[c];
            bz += b_z[c] * rz[c];
            ah += w_h[c] * rh[c];
            bh += b_h[c] * rh[c];
        }
        g_az[o] = az; g_bz[o] = bz + lb_z[o];
        g_ah[o] = ah; g_bh[o] = bh + lb_h[o];
        g_hw[o] = head_w[o];
    }
    if (o == 0) {
        float m = -1e30f;
        for (int t = 0; t < TT; t++) m = fmaxf(m, att[t]);
        float ex[TT]; float sum = 0.f;
        for (int t = 0; t < TT; t++) { ex[t] = expf(att[t] - m); sum += ex[t]; }
        for (int t = 0; t < TT; t++) g_probs[t] = 0.5f * ex[t] / sum;  // fold 0.5 of (1-z)
        g_hb = head_b[0];
    }
}

// ---- K2: dinv + y = dinv*x ; one thread per float4 chunk (3 per node) ----
__global__ void k_dinv_y(const float* __restrict__ x, int n3) {
    int j = blockIdx.x * blockDim.x + threadIdx.x;
    if (j >= n3) return;
    int node = j / 3;
    int part = j - node * 3;
    float di = rsqrtf(1.0f + g_deg[node]);   // +1 = self-loop weight; always > 0
    if (part == 0) g_dinv[node] = di;
    float4 v = __ldg(reinterpret_cast<const float4*>(x) + j);
    reinterpret_cast<float4*>(g_y)[j] = make_float4(di * v.x, di * v.y, di * v.z, di * v.w);
}

// ---- K3: cooperative 3-lane edge scatter  agg[d,:] += w * y[s,:] ----
// 3 lanes handle one edge (lane part p = float4 chunk p of the 48B row), so the
// gather and the RED for one row coalesce into single L1tex line-wavefronts.
__global__ void k_scatter3(const int* __restrict__ ei, const float* __restrict__ ew, int e) {
    int lane = threadIdx.x & 31;
    if (lane >= 30) return;
    int warp = (blockIdx.x * blockDim.x + threadIdx.x) >> 5;
    int grp  = lane / 3;               // 0..9
    int part = lane - grp * 3;         // 0..2
    int i = warp * 10 + grp;           // edge id
    if (i >= e) return;
    int s = __ldg(ei + i);
    int d = __ldg(ei + e + i);
    float w = __ldg(ew + i);
    float4 v = __ldg(reinterpret_cast<const float4*>(g_y + (size_t)s * TT) + part);
    red4(g_agg + (size_t)d * TT + part * 4, w * v.x, w * v.y, w * v.z, w * v.w);
}

// ---- K4: pointwise GRU-collapse, 4 threads per node (8 channels each) ----
// a[t] = dinv * (agg[t] + y[t]);  sigmoid via tanh: (1-z) = 0.5*(1 - tanh(zarg/2))
__global__ void k_final4(float* __restrict__ out, int n) {
    int tid = blockIdx.x * blockDim.x + threadIdx.x;
    int node = tid >> 2;
    int q = tid & 3;                   // channel-quarter 0..3
    if (node >= n) return;
    float di = g_dinv[node];
    float4* ap = reinterpret_cast<float4*>(g_agg + (size_t)node * TT);
    const float4* yp = reinterpret_cast<const float4*>(g_y + (size_t)node * TT);
    float4 a0 = ap[0], a1 = ap[1], a2 = ap[2];
    float4 y0 = yp[0], y1 = yp[1], y2 = yp[2];
    // distributed re-zero of scratch for next graph replay
    if (q < 3) ap[q] = make_float4(0.f, 0.f, 0.f, 0.f);
    else g_deg[node] = 0.0f;
    float a[TT] = {di*(a0.x+y0.x), di*(a0.y+y0.y), di*(a0.z+y0.z), di*(a0.w+y0.w),
                   di*(a1.x+y1.x), di*(a1.y+y1.y), di*(a1.z+y1.z), di*(a1.w+y1.w),
                   di*(a2.x+y2.x), di*(a2.y+y2.y), di*(a2.z+y2.z), di*(a2.w+y2.w)};
    float p[TT];
    #pragma unroll
    for (int t = 0; t < TT; t++) p[t] = g_probs[t];
    float acc = 0.f;
    int c0 = q * (CC / 4);
    #pragma unroll
    for (int cc = 0; cc < CC / 4; cc++) {
        int c = c0 + cc;
        float az = 0.5f * g_az[c], bz = 0.5f * g_bz[c];
        float ah = g_ah[c], bh = g_bh[c];
        float hw = g_hw[c];
        float hc = 0.f;
        #pragma unroll
        for (int t = 0; t < TT; t++) {
            float tz = tanh_fast(fmaf(a[t], az, bz));      // tanh(zarg/2)
            float th = tanh_fast(fmaf(a[t], ah, bh));
            hc = fmaf(p[t], (1.0f - tz) * th, hc);
        }
        acc = fmaf(fmaxf(hc, 0.f), hw, acc);
    }
    // reduce the 4 channel-quarters (lanes q=0..3 of the same node share a warp)
    acc += __shfl_xor_sync(0xFFFFFFFFu, acc, 1);
    acc += __shfl_xor_sync(0xFFFFFFFFu, acc, 2);
    if (q == 0) out[node] = acc + g_hb;
}

extern "C" void kernel_launch(void* const* d_in, const int* in_sizes, int n_in,
                              void* d_out, int out_size) {
    const float* x      = (const float*)d_in[0];
    const int*   ei     = (const int*)  d_in[1];
    const float* ew     = (const float*)d_in[2];
    const float* w_z    = (const float*)d_in[3];
    const float* b_z    = (const float*)d_in[4];
    // d_in[5], d_in[6]: w_r, b_r — reset gate multiplies H=0, unused
    const float* w_h    = (const float*)d_in[7];
    const float* b_h    = (const float*)d_in[8];
    const float* lw_z   = (const float*)d_in[9];
    const float* lb_z   = (const float*)d_in[10];
    // d_in[11], d_in[12]: lw_r, lb_r — unused
    const float* lw_h   = (const float*)d_in[13];
    const float* lb_h   = (const float*)d_in[14];
    const float* att    = (const float*)d_in[15];
    const float* head_w = (const float*)d_in[16];
    const float* head_b = (const float*)d_in[17];
    float* out = (float*)d_out;

    int n = in_sizes[0] / TT;       // x is [N, T]
    int e = in_sizes[2];            // edge_weight is [E]
    if (n > MAXN) n = MAXN;

    const int B = 256;
    int n3  = n * 3;
    int gn3 = (n3 + B - 1) / B;
    int gn4 = (n * 4 + B - 1) / B;
    int degBlocks = ((e + 3) / 4 + B - 1) / B;
    int gsc = (e + 79) / 80;        // 10 edges per warp, 8 warps/block

    k_deg_consts<<<degBlocks + 1, B>>>(ei, ew, e, degBlocks,
                                       w_z, b_z, w_h, b_h, lw_z, lb_z, lw_h, lb_h,
                                       att, head_w, head_b);
    k_dinv_y<<<gn3, B>>>(x, n3);
    k_scatter3<<<gsc, B>>>(ei, ew, e);
    k_final4<<<gn4, B>>>(out, n);
}